// round 11
// baseline (speedup 1.0000x reference)
#include <cuda_runtime.h>
#include <math.h>

#define B_ROWS 32768
#define C_CLS  1000
#define NBLK   (B_ROWS / 4)      /* 8192 blocks, 4 rows each (2 warps/row) */

// packed accumulator: bits[63:51] arrival count (8192 wraps to 0 at 2^64),
//                     bits[50:0]  biased fixed-point sum
__device__ unsigned long long g_acc;   // zero-init; self-resets each launch

typedef unsigned long long u64;

#define SCALE_F   33554432.0f            /* 2^25 */
#define INV_SCALE (1.0f / 33554432.0f)
#define BIAS_LL   (1ll << 36)
#define CNT_ONE   (1ull << 51)
#define SUB_SCALE 3.90625f               /* 1000/256: subsample -> full Z */

__device__ __forceinline__ float frcp(float x) {
    float r; asm("rcp.approx.f32 %0, %1;" : "=f"(r) : "f"(x)); return r;
}
__device__ __forceinline__ float fpow_fast(float x, float p) {
    float lg; asm("lg2.approx.f32 %0, %1;" : "=f"(lg) : "f"(x));
    float e = lg * p;
    float r; asm("ex2.approx.f32 %0, %1;" : "=f"(r) : "f"(e)); return r;
}
__device__ __forceinline__ u64 pk(float x, float y) {
    u64 r; asm("mov.b64 %0, {%1,%2};" : "=l"(r) : "f"(x), "f"(y)); return r;
}
__device__ __forceinline__ void upk(u64 v, float& x, float& y) {
    asm("mov.b64 {%0,%1}, %2;" : "=f"(x), "=f"(y) : "l"(v));
}
__device__ __forceinline__ u64 fma2(u64 a, u64 b, u64 c) {
    u64 d; asm("fma.rn.f32x2 %0, %1, %2, %3;" : "=l"(d) : "l"(a), "l"(b), "l"(c)); return d;
}
__device__ __forceinline__ u64 mul2(u64 a, u64 b) {
    u64 d; asm("mul.rn.f32x2 %0, %1, %2;" : "=l"(d) : "l"(a), "l"(b)); return d;
}
__device__ __forceinline__ u64 rcp2(u64 v) {      // 2x MUFU
    float x, y; upk(v, x, y);
    return pk(frcp(x), frcp(y));
}
__device__ __forceinline__ float wredux(float v) {
    #pragma unroll
    for (int o = 16; o; o >>= 1) v += __shfl_xor_sync(0xffffffffu, v, o);
    return v;
}

// packed rcp seed; no cross-field borrow for nr in [-inf,-1]
#define MAGIC2 0xFEF311C3FEF311C3ULL

// Subsampled Z partial over pairs 0..NPAIR-1 (mask-free for both halves).
template<int NPAIR, int NSTEP>
__device__ __forceinline__ float zpass_sub(const u64* u2, float s)
{
    const u64 nONE2 = pk(-1.0f, -1.0f);
    const u64 TWO2  = pk(2.0f, 2.0f);
    const u64 nsv   = pk(-s, -s);
    u64 z2 = pk(0.0f, 0.0f);
    #pragma unroll
    for (int i = 0; i < NPAIR; ++i) {
        u64 nr2 = fma2(u2[i], nsv, nONE2);     // -(1+u*s)
        u64 y   = MAGIC2 - nr2;                // ~5% seed (ALU pipe)
        #pragma unroll
        for (int n = 0; n < NSTEP; ++n)
            y = mul2(y, fma2(nr2, y, TWO2));   // Newton
        u64 q2 = mul2(y, y);
        u64 q4 = mul2(q2, q2);
        z2 = fma2(q4, y, z2);                  // += r^-5
    }
    float zx, zy; upk(z2, zx, zy);
    return wredux(zx + zy);
}

// ---------------------------------------------------------------------------
// TWO warps per row (16 elems/lane, 8 packed f32x2 regs) for occupancy.
// Block = 8 warps = 4 rows.  Cross-warp reductions via smem + syncthreads.
// Algorithm identical to R10: subsample bootstrap (s1 seed-only, s_pred
// 1-Newton), full pass at s_pred accumulating Z5,Z6,S1,S2,S6,S7, Newton
// fixed-point extrapolation sf via g' = g(1-Z6/Z5)/s_pred, first-order
// weighted-sum corrections, scalar truth-class fix, fence-free packed-u64
// atomic finish.
// ---------------------------------------------------------------------------
__global__ __launch_bounds__(256, 5)
void bitempered_row_kernel(const float* __restrict__ logits,
                           const int*   __restrict__ truth,
                           const float* __restrict__ weight,
                           float* __restrict__ out,
                           float A_off, float B_off, float dA, float dB)
{
    __shared__ float smx[8], smza[8], smzb[8];
    __shared__ float smf[8][6];
    __shared__ float smacc[4];
    __shared__ u64   sm_total;
    __shared__ int   sm_last;

    const int lane = threadIdx.x & 31;
    const int wib  = threadIdx.x >> 5;
    const int rix  = wib >> 1;          // row within block (0..3)
    const int half = wib & 1;           // which half of the row
    const int row  = blockIdx.x * 4 + rix;

    const int   t  = truth[row];
    const float xt = logits[(size_t)row * C_CLS + t];
    const float wt = __ldg(weight + t);

    const float4* xrow = (const float4*)(logits + (size_t)row * C_CLS);
    const float4* w4   = (const float4*)weight;

    u64 u2[8];
    float xmax = -INFINITY;
    #pragma unroll
    for (int j = 0; j < 4; ++j) {
        const int q = half * 128 + lane + 32 * j;   // float4 idx, valid iff q<250
        float4 v;
        if (q < 250) v = xrow[q];
        else         v = make_float4(-INFINITY, -INFINITY, -INFINITY, -INFINITY);
        u2[2*j]   = pk(v.x, v.y);
        u2[2*j+1] = pk(v.z, v.w);
        xmax = fmaxf(xmax, fmaxf(fmaxf(v.x, v.y), fmaxf(v.z, v.w)));
    }
    xmax = fmaxf(xmax, __shfl_xor_sync(0xffffffffu, xmax, 16));
    xmax = fmaxf(xmax, __shfl_xor_sync(0xffffffffu, xmax, 8));
    xmax = fmaxf(xmax, __shfl_xor_sync(0xffffffffu, xmax, 4));
    xmax = fmaxf(xmax, __shfl_xor_sync(0xffffffffu, xmax, 2));
    xmax = fmaxf(xmax, __shfl_xor_sync(0xffffffffu, xmax, 1));
    if (lane == 0) smx[wib] = xmax;
    __syncthreads();
    xmax = fmaxf(smx[2*rix], smx[2*rix + 1]);       // row max

    {
        const u64 cm = pk(-0.2f, -0.2f);
        const u64 ca = pk(0.2f * xmax, 0.2f * xmax);
        #pragma unroll
        for (int i = 0; i < 8; ++i)
            u2[i] = fma2(u2[i], cm, ca);            // masked raw -inf -> +inf
    }

    // Bootstrap on 256-elem row subsample (pairs 0,1 of each half)
    float zw = zpass_sub<2, 0>(u2, 1.0f);
    if (lane == 0) smza[wib] = zw;
    __syncthreads();
    const float s1 = fpow_fast((smza[2*rix] + smza[2*rix+1]) * SUB_SCALE, -0.2f);

    zw = zpass_sub<2, 1>(u2, s1);
    if (lane == 0) smzb[wib] = zw;
    __syncthreads();
    const float s_pred = fpow_fast((smzb[2*rix] + smzb[2*rix+1]) * SUB_SCALE, -0.2f);

    // Full pass at s_pred
    const u64 ONE2  = pk(1.0f, 1.0f);
    const u64 nONE2 = pk(-1.0f, -1.0f);
    const u64 TWO2  = pk(2.0f, 2.0f);
    const u64 sv    = pk(s_pred, s_pred);
    const u64 nsv   = pk(-s_pred, -s_pred);

    u64 z5a = pk(0.0f, 0.0f);
    u64 z6a = z5a, S1a = z5a, S2a = z5a, S6a = z5a, S7a = z5a;
    #pragma unroll
    for (int j = 0; j < 4; ++j) {
        const int q = half * 128 + lane + 32 * j;
        float4 wv;
        if (q < 250) wv = w4[q];
        else         wv = make_float4(0.0f, 0.0f, 0.0f, 0.0f);
        u64 w2[2] = { pk(wv.x, wv.y), pk(wv.z, wv.w) };
        const bool newton_ok = (half == 0) || (j < 3);   // masked pairs: MUFU
        #pragma unroll
        for (int h = 0; h < 2; ++h) {
            const int i = 2*j + h;
            u64 y;
            if (newton_ok) {                    // mask-free: FMA-pipe Newton
                u64 nr2 = fma2(u2[i], nsv, nONE2);
                y = MAGIC2 - nr2;
                y = mul2(y, fma2(nr2, y, TWO2));
                y = mul2(y, fma2(nr2, y, TWO2));
            } else {                            // MUFU (inf-safe: inv -> 0)
                u64 r2 = fma2(u2[i], sv, ONE2);
                y = rcp2(r2);
            }
            u64 q2 = mul2(y, y);
            u64 q4 = mul2(q2, q2);
            z5a = fma2(q4, y, z5a);             // Z5 += inv^5
            u64 p6 = mul2(q4, q2);
            z6a = fma2(p6, ONE2, z6a);          // Z6 += inv^6
            S1a = fma2(y,  w2[h], S1a);         // += w*inv
            S2a = fma2(q2, w2[h], S2a);         // += w*inv^2
            S6a = fma2(p6, w2[h], S6a);         // += w*inv^6
            u64 p7 = mul2(p6, y);
            S7a = fma2(p7, w2[h], S7a);         // += w*inv^7
        }
    }
    {
        float a, b;
        upk(z5a, a, b); float v0 = wredux(a + b);
        upk(z6a, a, b); float v1 = wredux(a + b);
        upk(S1a, a, b); float v2 = wredux(a + b);
        upk(S2a, a, b); float v3 = wredux(a + b);
        upk(S6a, a, b); float v4 = wredux(a + b);
        upk(S7a, a, b); float v5 = wredux(a + b);
        if (lane == 0) {
            smf[wib][0] = v0; smf[wib][1] = v1; smf[wib][2] = v2;
            smf[wib][3] = v3; smf[wib][4] = v4; smf[wib][5] = v5;
        }
    }
    __syncthreads();

    if (half == 0 && lane == 0) {
        const float Z5 = smf[2*rix][0] + smf[2*rix+1][0];
        const float Z6 = smf[2*rix][1] + smf[2*rix+1][1];
        const float S1 = smf[2*rix][2] + smf[2*rix+1][2];
        const float S2 = smf[2*rix][3] + smf[2*rix+1][3];
        const float S6 = smf[2*rix][4] + smf[2*rix+1][4];
        const float S7 = smf[2*rix][5] + smf[2*rix+1][5];

        const float g  = fpow_fast(Z5, -0.2f);                        // g(s_pred)
        const float gp = g * (1.0f - Z6 * frcp(Z5)) * frcp(s_pred);   // g'(s_pred)
        const float sf = s_pred + (g - s_pred) * frcp(1.0f - gp);     // Newton FP
        const float zp = frcp(sf);                 // u + zp = 1 - 0.2*(x-nc)
        const float c  = fmaf(sf, frcp(s_pred), -1.0f);
        const float sf2 = sf * sf;
        const float sf6 = sf2 * sf2 * sf2;
        const float sumInv  = sf  * fmaf(-c, S1 - S2, S1);
        const float sumInv6 = sf6 * fmaf(-6.0f * c, S6 - S7, S6);
        const float ut   = fmaf(xt, -0.2f, 0.2f * xmax);
        const float invt = frcp(ut + zp);
        float acc = fmaf(-B_off, sumInv, sumInv6 * (1.0f / 1.2f));
        acc += wt * fmaf(-dB, invt, dA);
        smacc[rix] = acc;
    }
    __syncthreads();

    if (threadIdx.x == 0) {
        float bs = smacc[0] + smacc[1] + smacc[2] + smacc[3];
        long long llv = __float2ll_rn(bs * SCALE_F);        // |llv| << 2^36
        u64 contrib = CNT_ONE + (u64)(llv + BIAS_LL);
        u64 old = atomicAdd(&g_acc, contrib);
        int last = ((old >> 51) == (u64)(NBLK - 1));
        sm_last = last;
        if (last) sm_total = old + contrib;   // counter bits wrapped to 0 exactly
    }
    __syncthreads();

    // last-arriving block finishes (atomic return already holds the full sum)
    if (sm_last && wib == 0) {
        float ws = 0.0f;
        #pragma unroll
        for (int j = 0; j < 8; ++j) {
            const int q = lane + 32 * j;
            if (q < 250) {
                float4 wv = w4[q];
                ws += (wv.x + wv.y) + (wv.z + wv.w);
            }
        }
        ws = wredux(ws);
        if (lane == 0) {
            long long net = (long long)sm_total - ((long long)NBLK * BIAS_LL);
            const float lsum = (float)net * INV_SCALE;
            out[0] = lsum * ((float)C_CLS / ws) * (1.0f / (float)B_ROWS)
                   + A_off * (float)C_CLS;
            atomicExch(&g_acc, 0ull);          // reset for next graph replay
        }
    }
}

// ---------------------------------------------------------------------------
extern "C" void kernel_launch(void* const* d_in, const int* in_sizes, int n_in,
                              void* d_out, int out_size)
{
    const float* logits = (const float*)d_in[0];
    const int*   truth  = (const int*)  d_in[1];
    const float* weight = (const float*)d_in[2];
    float* out = (float*)d_out;

    const double T1 = 0.8, SM = 0.05;
    const double Cd = (double)C_CLS;
    const double y_on  = (1.0 - SM * Cd / (Cd - 1.0)) + SM / (Cd - 1.0);
    const double y_off = SM / (Cd - 1.0);
    auto logt1 = [](double v) { return (pow(v, 0.2) - 1.0) / 0.2; };
    auto Cy = [&](double y) {
        return y * logt1(y + 1e-10) - pow(y, 2.0 - T1) / (2.0 - T1);
    };
    const float A_on  = (float)(Cy(y_on)  + 5.0 * y_on);
    const float A_off = (float)(Cy(y_off) + 5.0 * y_off);
    const float B_on  = (float)(5.0 * y_on);
    const float B_off = (float)(5.0 * y_off);

    bitempered_row_kernel<<<NBLK, 256>>>(logits, truth, weight, out,
                                         A_off, B_off,
                                         A_on - A_off, B_on - B_off);
}

// round 12
// speedup vs baseline: 1.3330x; 1.3330x over previous
#include <cuda_runtime.h>
#include <math.h>

#define B_ROWS 32768
#define C_CLS  1000
#define NBLK   (B_ROWS / 8)

// packed accumulator: bits[63:52] arrival count, bits[51:0] biased fixed-point sum
__device__ unsigned long long g_acc;   // zero-init; self-resets each launch

typedef unsigned long long u64;

#define SCALE_F   268435456.0f           /* 2^28 */
#define INV_SCALE (1.0f / 268435456.0f)
#define BIAS_LL   (1ll << 39)
#define SUB_SCALE 3.90625f               /* 1000/256: subsample -> full Z */

__device__ __forceinline__ float frcp(float x) {
    float r; asm("rcp.approx.f32 %0, %1;" : "=f"(r) : "f"(x)); return r;
}
__device__ __forceinline__ float fpow_fast(float x, float p) {
    float lg; asm("lg2.approx.f32 %0, %1;" : "=f"(lg) : "f"(x));
    float e = lg * p;
    float r; asm("ex2.approx.f32 %0, %1;" : "=f"(r) : "f"(e)); return r;
}
__device__ __forceinline__ u64 pk(float x, float y) {
    u64 r; asm("mov.b64 %0, {%1,%2};" : "=l"(r) : "f"(x), "f"(y)); return r;
}
__device__ __forceinline__ void upk(u64 v, float& x, float& y) {
    asm("mov.b64 {%0,%1}, %2;" : "=f"(x), "=f"(y) : "l"(v));
}
__device__ __forceinline__ u64 fma2(u64 a, u64 b, u64 c) {
    u64 d; asm("fma.rn.f32x2 %0, %1, %2, %3;" : "=l"(d) : "l"(a), "l"(b), "l"(c)); return d;
}
__device__ __forceinline__ u64 mul2(u64 a, u64 b) {
    u64 d; asm("mul.rn.f32x2 %0, %1, %2;" : "=l"(d) : "l"(a), "l"(b)); return d;
}
__device__ __forceinline__ u64 add2(u64 a, u64 b) {
    u64 d; asm("add.rn.f32x2 %0, %1, %2;" : "=l"(d) : "l"(a), "l"(b)); return d;
}
__device__ __forceinline__ u64 rcp2(u64 v) {      // 2x MUFU
    float x, y; upk(v, x, y);
    return pk(frcp(x), frcp(y));
}
__device__ __forceinline__ float wredux(float v) {
    #pragma unroll
    for (int o = 16; o; o >>= 1) v += __shfl_xor_sync(0xffffffffu, v, o);
    return v;
}
// 64-bit packed butterfly reduction: reduces both packed floats at once
__device__ __forceinline__ u64 wredux2(u64 v) {
    #pragma unroll
    for (int o = 16; o; o >>= 1)
        v = add2(v, __shfl_xor_sync(0xffffffffu, v, o));
    return v;
}

// packed rcp seed; no cross-field borrow: low field >= bits(nr) for nr in [-3,-1]
#define MAGIC2 0xFEF311C3FEF311C3ULL

// Subsampled Z pass over pairs 0..NPAIR-1 (all mask-free): Z = sum (1+u*s)^-5.
template<int NPAIR, int NSTEP>
__device__ __forceinline__ float zpass_sub(const u64* u2, float s)
{
    const u64 nONE2 = pk(-1.0f, -1.0f);
    const u64 TWO2  = pk(2.0f, 2.0f);
    const u64 nsv   = pk(-s, -s);
    u64 z2 = pk(0.0f, 0.0f);
    #pragma unroll
    for (int i = 0; i < NPAIR; ++i) {
        u64 nr2 = fma2(u2[i], nsv, nONE2);     // -(1+u*s) in [-3,-1]
        u64 y   = MAGIC2 - nr2;                // ~5% seed (ALU pipe)
        #pragma unroll
        for (int n = 0; n < NSTEP; ++n)
            y = mul2(y, fma2(nr2, y, TWO2));   // Newton
        u64 q2 = mul2(y, y);
        u64 q4 = mul2(q2, q2);
        z2 = fma2(q4, y, z2);                  // += r^-5
    }
    float zx, zy; upk(z2, zx, zy);
    return wredux(zx + zy);
}

// ---------------------------------------------------------------------------
// One warp per row; 32 elems/lane as 16 packed f32x2 regs (R10 structure —
// the proven fastest layout; R11's 2-warp split regressed).
// Subsample bootstrap: s1 = g~sub(1) seed-only, s_pred = g~sub(s1) 1-Newton.
// Full pass at s_pred accumulates Z5, Z6 (unweighted) and S1, S6, S7 (w-sums).
// Newton fixed-point extrapolation: g' = g(1-Z6/Z5)/s_pred,
//   sf = s_pred + (g-s_pred)/(1-g').  c = sf/s_pred - 1 (~6e-3):
//   Σw/(u+zp)   ≈ sf·S1                          (B_off term; O(c) negligible)
//   Σw/(u+zp)^6 ≈ sf⁶·(S6 - 6c(S6-S7))
// Fence-free packed-u64 atomic finish.
// ---------------------------------------------------------------------------
__global__ __launch_bounds__(256, 4)
void bitempered_row_kernel(const float* __restrict__ logits,
                           const int*   __restrict__ truth,
                           const float* __restrict__ weight,
                           float* __restrict__ out,
                           float A_off, float B_off, float dA, float dB)
{
    __shared__ float sm[8];
    __shared__ u64   sm_total;
    __shared__ int   sm_last;
    const int lane = threadIdx.x & 31;
    const int wib  = threadIdx.x >> 5;
    const int row  = blockIdx.x * 8 + wib;

    const int   t  = truth[row];                       // uniform per warp
    const float xt = logits[(size_t)row * C_CLS + t];  // truth-class logit
    const float wt = __ldg(weight + t);

    const float4* xrow = (const float4*)(logits + (size_t)row * C_CLS);

    u64 u2[16];
    float xmax = -INFINITY;
    #pragma unroll
    for (int j = 0; j < 8; ++j) {
        const int q = lane + 32 * j;            // float4 index, valid iff q < 250
        float4 v;
        if (q < 250) v = xrow[q];
        else         v = make_float4(-INFINITY, -INFINITY, -INFINITY, -INFINITY);
        u2[2*j]   = pk(v.x, v.y);
        u2[2*j+1] = pk(v.z, v.w);
        xmax = fmaxf(xmax, fmaxf(fmaxf(v.x, v.y), fmaxf(v.z, v.w)));
    }
    #pragma unroll
    for (int o = 16; o; o >>= 1)
        xmax = fmaxf(xmax, __shfl_xor_sync(0xffffffffu, xmax, o));

    {
        const u64 cm = pk(-0.2f, -0.2f);
        const u64 ca = pk(0.2f * xmax, 0.2f * xmax);
        #pragma unroll
        for (int i = 0; i < 16; ++i)
            u2[i] = fma2(u2[i], cm, ca);        // masked raw -inf -> +inf
    }

    // Subsampled bootstrap (sampling err ~3% on Z -> ~0.6% on s)
    const float s1     = fpow_fast(zpass_sub<4,0>(u2, 1.0f) * SUB_SCALE, -0.2f);
    const float s_pred = fpow_fast(zpass_sub<4,1>(u2, s1)   * SUB_SCALE, -0.2f);

    // Full pass at s_pred: Z5, Z6 + weighted sums S1, S6, S7
    const u64 ONE2  = pk(1.0f, 1.0f);
    const u64 nONE2 = pk(-1.0f, -1.0f);
    const u64 TWO2  = pk(2.0f, 2.0f);
    const u64 sv    = pk(s_pred, s_pred);
    const u64 nsv   = pk(-s_pred, -s_pred);
    const float4* w4 = (const float4*)weight;

    u64 z5a = pk(0.0f, 0.0f);
    u64 z6a = z5a, S1a = z5a, S6a = z5a, S7a = z5a;
    #pragma unroll
    for (int j = 0; j < 8; ++j) {
        const int q = lane + 32 * j;
        float4 wv;
        if (q < 250) wv = w4[q];
        else         wv = make_float4(0.0f, 0.0f, 0.0f, 0.0f);
        u64 w2[2] = { pk(wv.x, wv.y), pk(wv.z, wv.w) };
        #pragma unroll
        for (int h = 0; h < 2; ++h) {
            const int i = 2*j + h;
            u64 y;
            if (i < 14) {                       // mask-free: FMA-pipe Newton
                u64 nr2 = fma2(u2[i], nsv, nONE2);
                y = MAGIC2 - nr2;
                y = mul2(y, fma2(nr2, y, TWO2));
                y = mul2(y, fma2(nr2, y, TWO2));
            } else {                            // MUFU (inf-safe: inv -> 0)
                u64 r2 = fma2(u2[i], sv, ONE2);
                y = rcp2(r2);
            }
            u64 q2 = mul2(y, y);
            u64 q4 = mul2(q2, q2);
            z5a = fma2(q4, y, z5a);             // Z5 += inv^5
            u64 p6 = mul2(q4, q2);
            z6a = add2(z6a, p6);                // Z6 += inv^6
            S1a = fma2(y,  w2[h], S1a);         // += w*inv
            S6a = fma2(p6, w2[h], S6a);         // += w*inv^6
            u64 p7 = mul2(p6, y);
            S7a = fma2(p7, w2[h], S7a);         // += w*inv^7
        }
    }
    // pair up the 5 horizontal sums into packed reductions
    float a, b, a2, b2;
    upk(z5a, a, b); upk(z6a, a2, b2);
    u64 rZ = wredux2(pk(a + b, a2 + b2));              // (Z5, Z6)
    upk(S1a, a, b); upk(S6a, a2, b2);
    u64 rS = wredux2(pk(a + b, a2 + b2));              // (S1, S6)
    upk(S7a, a, b);
    const float S7 = wredux(a + b);

    if (lane == 0) {
        float Z5, Z6, S1, S6;
        upk(rZ, Z5, Z6);
        upk(rS, S1, S6);
        const float g  = fpow_fast(Z5, -0.2f);                        // g(s_pred)
        const float gp = g * (1.0f - Z6 * frcp(Z5)) * frcp(s_pred);   // g'(s_pred)
        const float sf = s_pred + (g - s_pred) * frcp(1.0f - gp);     // Newton FP
        const float zp = frcp(sf);                    // u + zp = 1 - 0.2*(x-nc)
        const float c  = fmaf(sf, frcp(s_pred), -1.0f);
        const float sf2 = sf * sf;
        const float sf6 = sf2 * sf2 * sf2;
        const float sumInv  = sf * S1;
        const float sumInv6 = sf6 * fmaf(-6.0f * c, S6 - S7, S6);
        const float ut   = fmaf(xt, -0.2f, 0.2f * xmax);
        const float invt = frcp(ut + zp);
        float acc = fmaf(-B_off, sumInv, sumInv6 * (1.0f / 1.2f));
        acc += wt * fmaf(-dB, invt, dA);
        sm[wib] = acc;
    }
    __syncthreads();

    if (threadIdx.x == 0) {
        float bs = 0.0f;
        #pragma unroll
        for (int i = 0; i < 8; ++i) bs += sm[i];
        long long llv = __float2ll_rn(bs * SCALE_F);        // |llv| << 2^39
        u64 contrib = (1ull << 52) + (u64)(llv + BIAS_LL);
        u64 old = atomicAdd(&g_acc, contrib);
        int last = ((old >> 52) == (u64)(NBLK - 1));
        sm_last = last;
        if (last) sm_total = old + contrib;   // counter bits wrapped to 0 exactly
    }
    __syncthreads();

    // last-arriving block finishes (atomic return already holds the full sum)
    if (sm_last && wib == 0) {
        float ws = 0.0f;
        #pragma unroll
        for (int j = 0; j < 8; ++j) {
            const int q = lane + 32 * j;
            if (q < 250) {
                float4 wv = w4[q];
                ws += (wv.x + wv.y) + (wv.z + wv.w);
            }
        }
        ws = wredux(ws);
        if (lane == 0) {
            long long net = (long long)sm_total - ((long long)NBLK * BIAS_LL);
            const float lsum = (float)net * INV_SCALE;
            out[0] = lsum * ((float)C_CLS / ws) * (1.0f / (float)B_ROWS)
                   + A_off * (float)C_CLS;
            atomicExch(&g_acc, 0ull);          // reset for next graph replay
        }
    }
}

// ---------------------------------------------------------------------------
extern "C" void kernel_launch(void* const* d_in, const int* in_sizes, int n_in,
                              void* d_out, int out_size)
{
    const float* logits = (const float*)d_in[0];
    const int*   truth  = (const int*)  d_in[1];
    const float* weight = (const float*)d_in[2];
    float* out = (float*)d_out;

    const double T1 = 0.8, SM = 0.05;
    const double Cd = (double)C_CLS;
    const double y_on  = (1.0 - SM * Cd / (Cd - 1.0)) + SM / (Cd - 1.0);
    const double y_off = SM / (Cd - 1.0);
    auto logt1 = [](double v) { return (pow(v, 0.2) - 1.0) / 0.2; };
    auto Cy = [&](double y) {
        return y * logt1(y + 1e-10) - pow(y, 2.0 - T1) / (2.0 - T1);
    };
    const float A_on  = (float)(Cy(y_on)  + 5.0 * y_on);
    const float A_off = (float)(Cy(y_off) + 5.0 * y_off);
    const float B_on  = (float)(5.0 * y_on);
    const float B_off = (float)(5.0 * y_off);

    bitempered_row_kernel<<<NBLK, 256>>>(logits, truth, weight, out,
                                         A_off, B_off,
                                         A_on - A_off, B_on - B_off);
}

// round 13
// speedup vs baseline: 1.4177x; 1.0635x over previous
#include <cuda_runtime.h>
#include <math.h>

#define B_ROWS 32768
#define C_CLS  1000
#define NBLK   (B_ROWS / 8)

// packed accumulator: bits[63:52] arrival count, bits[51:0] biased fixed-point sum
__device__ unsigned long long g_acc;   // zero-init; self-resets each launch

typedef unsigned long long u64;

#define SCALE_F   268435456.0f           /* 2^28 */
#define INV_SCALE (1.0f / 268435456.0f)
#define BIAS_LL   (1ll << 39)
#define SUB_SCALE 3.90625f               /* 1000/256: subsample -> full Z */
#define S0_BOOT   0.35f                  /* fixed bootstrap start; any [0.2,0.5]
                                            works (extrapolation absorbs e0) */

__device__ __forceinline__ float frcp(float x) {
    float r; asm("rcp.approx.f32 %0, %1;" : "=f"(r) : "f"(x)); return r;
}
__device__ __forceinline__ float fpow_fast(float x, float p) {
    float lg; asm("lg2.approx.f32 %0, %1;" : "=f"(lg) : "f"(x));
    float e = lg * p;
    float r; asm("ex2.approx.f32 %0, %1;" : "=f"(r) : "f"(e)); return r;
}
__device__ __forceinline__ u64 pk(float x, float y) {
    u64 r; asm("mov.b64 %0, {%1,%2};" : "=l"(r) : "f"(x), "f"(y)); return r;
}
__device__ __forceinline__ void upk(u64 v, float& x, float& y) {
    asm("mov.b64 {%0,%1}, %2;" : "=f"(x), "=f"(y) : "l"(v));
}
__device__ __forceinline__ u64 fma2(u64 a, u64 b, u64 c) {
    u64 d; asm("fma.rn.f32x2 %0, %1, %2, %3;" : "=l"(d) : "l"(a), "l"(b), "l"(c)); return d;
}
__device__ __forceinline__ u64 mul2(u64 a, u64 b) {
    u64 d; asm("mul.rn.f32x2 %0, %1, %2;" : "=l"(d) : "l"(a), "l"(b)); return d;
}
__device__ __forceinline__ u64 add2(u64 a, u64 b) {
    u64 d; asm("add.rn.f32x2 %0, %1, %2;" : "=l"(d) : "l"(a), "l"(b)); return d;
}
__device__ __forceinline__ u64 rcp2(u64 v) {      // 2x MUFU
    float x, y; upk(v, x, y);
    return pk(frcp(x), frcp(y));
}
__device__ __forceinline__ float wredux(float v) {
    #pragma unroll
    for (int o = 16; o; o >>= 1) v += __shfl_xor_sync(0xffffffffu, v, o);
    return v;
}
// 64-bit packed butterfly reduction: both packed floats at once
__device__ __forceinline__ u64 wredux2(u64 v) {
    #pragma unroll
    for (int o = 16; o; o >>= 1)
        v = add2(v, __shfl_xor_sync(0xffffffffu, v, o));
    return v;
}

// packed rcp seed; no cross-field borrow: low field >= bits(nr) for nr in [-3,-1]
#define MAGIC2 0xFEF311C3FEF311C3ULL

// ---------------------------------------------------------------------------
// One warp per row; 32 RAW logits/lane as 16 packed f32x2 regs (no separate
// u-preprocessing: each pass folds u = -0.2(x-mu) into its linear constants:
//   -r = (0.2s)*x - (1 + 0.2s*xmax) ).
// Bootstrap: ONE subsample pass (pairs 0..3, 256 elems, seed+1-Newton) at
// fixed s0, accumulating Z5s,Z6s; Newton fixed-point extrapolation gives
// s_pred (err ~1%: sampling 0.6% + quadratic residual).
// Full pass at s_pred: Z5, Z6 (unweighted), S1, S6, S7 (w-sums); second
// Newton FP extrapolation -> sf; first-order corrected sums:
//   Σw/(u+zp)   ≈ sf·S1            Σw/(u+zp)^6 ≈ sf⁶·(S6 - 6c(S6-S7))
// Fence-free packed-u64 atomic finish.
// ---------------------------------------------------------------------------
__global__ __launch_bounds__(256, 4)
void bitempered_row_kernel(const float* __restrict__ logits,
                           const int*   __restrict__ truth,
                           const float* __restrict__ weight,
                           float* __restrict__ out,
                           float A_off, float B_off, float dA, float dB)
{
    __shared__ float sm[8];
    __shared__ u64   sm_total;
    __shared__ int   sm_last;
    const int lane = threadIdx.x & 31;
    const int wib  = threadIdx.x >> 5;
    const int row  = blockIdx.x * 8 + wib;

    const int   t  = truth[row];                       // uniform per warp
    const float xt = logits[(size_t)row * C_CLS + t];  // truth-class logit
    const float wt = __ldg(weight + t);

    const float4* xrow = (const float4*)(logits + (size_t)row * C_CLS);

    u64 x2[16];                                 // raw logits (masked = -inf)
    float xmax = -INFINITY;
    #pragma unroll
    for (int j = 0; j < 8; ++j) {
        const int q = lane + 32 * j;            // float4 index, valid iff q < 250
        float4 v;
        if (q < 250) v = xrow[q];
        else         v = make_float4(-INFINITY, -INFINITY, -INFINITY, -INFINITY);
        x2[2*j]   = pk(v.x, v.y);
        x2[2*j+1] = pk(v.z, v.w);
        xmax = fmaxf(xmax, fmaxf(fmaxf(v.x, v.y), fmaxf(v.z, v.w)));
    }
    #pragma unroll
    for (int o = 16; o; o >>= 1)
        xmax = fmaxf(xmax, __shfl_xor_sync(0xffffffffu, xmax, o));

    const u64 TWO2 = pk(2.0f, 2.0f);

    // ---- Bootstrap: one subsample pass at s0, with Newton FP extrapolation
    float s_pred;
    {
        const float m  = 0.2f * S0_BOOT;
        const float cc = fmaf(m, xmax, 1.0f);   // 1 + 0.2*s0*xmax
        const u64 pm2 = pk(m, m);
        const u64 nc2 = pk(-cc, -cc);
        u64 z5a = pk(0.0f, 0.0f), z6a = z5a;
        #pragma unroll
        for (int i = 0; i < 4; ++i) {           // pairs 0..3: mask-free
            u64 nr2 = fma2(x2[i], pm2, nc2);    // -(1+u*s0) in [-3,-1]
            u64 y   = MAGIC2 - nr2;             // ~5% seed (ALU pipe)
            y = mul2(y, fma2(nr2, y, TWO2));    // 1 Newton (~1e-3)
            u64 q2 = mul2(y, y);
            u64 q4 = mul2(q2, q2);
            z5a = fma2(q4, y, z5a);             // += inv^5
            u64 p6 = mul2(q4, q2);
            z6a = add2(z6a, p6);                // += inv^6
        }
        float a, b, a2, b2;
        upk(z5a, a, b); upk(z6a, a2, b2);
        u64 rZ = wredux2(pk(a + b, a2 + b2));   // all lanes get (Z5s, Z6s)
        float Z5s, Z6s; upk(rZ, Z5s, Z6s);
        const float Z5 = Z5s * SUB_SCALE;
        const float g  = fpow_fast(Z5, -0.2f);                  // g(s0)
        const float gp = g * (1.0f - Z6s * frcp(Z5s)) * (1.0f / S0_BOOT);
        s_pred = S0_BOOT + (g - S0_BOOT) * frcp(1.0f - gp);     // Newton FP
    }

    // ---- Full pass at s_pred: Z5, Z6 + weighted sums S1, S6, S7
    const float m  = 0.2f * s_pred;
    const float cc = fmaf(m, xmax, 1.0f);       // 1 + 0.2*s_pred*xmax
    const u64 pm2  = pk(m, m);                  // for nr (Newton path)
    const u64 nc2  = pk(-cc, -cc);
    const u64 nm2  = pk(-m, -m);                // for r  (MUFU path)
    const u64 pc2  = pk(cc, cc);
    const float4* w4 = (const float4*)weight;

    u64 z5a = pk(0.0f, 0.0f);
    u64 z6a = z5a, S1a = z5a, S6a = z5a, S7a = z5a;
    #pragma unroll
    for (int j = 0; j < 8; ++j) {
        const int q = lane + 32 * j;
        float4 wv;
        if (q < 250) wv = w4[q];
        else         wv = make_float4(0.0f, 0.0f, 0.0f, 0.0f);
        u64 w2[2] = { pk(wv.x, wv.y), pk(wv.z, wv.w) };
        #pragma unroll
        for (int h = 0; h < 2; ++h) {
            const int i = 2*j + h;
            u64 y;
            if (i < 14) {                       // mask-free: FMA-pipe Newton
                u64 nr2 = fma2(x2[i], pm2, nc2);     // -(1+u*s)
                y = MAGIC2 - nr2;
                y = mul2(y, fma2(nr2, y, TWO2));
                y = mul2(y, fma2(nr2, y, TWO2));
            } else {                            // MUFU (x=-inf -> r=+inf -> 0)
                u64 r2 = fma2(x2[i], nm2, pc2);
                y = rcp2(r2);
            }
            u64 q2 = mul2(y, y);
            u64 q4 = mul2(q2, q2);
            z5a = fma2(q4, y, z5a);             // Z5 += inv^5
            u64 p6 = mul2(q4, q2);
            z6a = add2(z6a, p6);                // Z6 += inv^6
            S1a = fma2(y,  w2[h], S1a);         // += w*inv
            S6a = fma2(p6, w2[h], S6a);         // += w*inv^6
            u64 p7 = mul2(p6, y);
            S7a = fma2(p7, w2[h], S7a);         // += w*inv^7
        }
    }
    // pack the 5 horizontal sums into 2.5 packed reductions
    float a, b, a2, b2;
    upk(z5a, a, b); upk(z6a, a2, b2);
    u64 rZ = wredux2(pk(a + b, a2 + b2));              // (Z5, Z6)
    upk(S1a, a, b); upk(S6a, a2, b2);
    u64 rS = wredux2(pk(a + b, a2 + b2));              // (S1, S6)
    upk(S7a, a, b);
    const float S7 = wredux(a + b);

    if (lane == 0) {
        float Z5, Z6, S1, S6;
        upk(rZ, Z5, Z6);
        upk(rS, S1, S6);
        const float g  = fpow_fast(Z5, -0.2f);                        // g(s_pred)
        const float gp = g * (1.0f - Z6 * frcp(Z5)) * frcp(s_pred);   // g'(s_pred)
        const float sf = s_pred + (g - s_pred) * frcp(1.0f - gp);     // Newton FP
        const float zp = frcp(sf);                    // u + zp = 1 - 0.2*(x-nc)
        const float c  = fmaf(sf, frcp(s_pred), -1.0f);
        const float sf2 = sf * sf;
        const float sf6 = sf2 * sf2 * sf2;
        const float sumInv  = sf * S1;
        const float sumInv6 = sf6 * fmaf(-6.0f * c, S6 - S7, S6);
        const float ut   = fmaf(xt, -0.2f, 0.2f * xmax);
        const float invt = frcp(ut + zp);
        float acc = fmaf(-B_off, sumInv, sumInv6 * (1.0f / 1.2f));
        acc += wt * fmaf(-dB, invt, dA);
        sm[wib] = acc;
    }
    __syncthreads();

    if (threadIdx.x == 0) {
        float bs = 0.0f;
        #pragma unroll
        for (int i = 0; i < 8; ++i) bs += sm[i];
        long long llv = __float2ll_rn(bs * SCALE_F);        // |llv| << 2^39
        u64 contrib = (1ull << 52) + (u64)(llv + BIAS_LL);
        u64 old = atomicAdd(&g_acc, contrib);
        int last = ((old >> 52) == (u64)(NBLK - 1));
        sm_last = last;
        if (last) sm_total = old + contrib;   // counter bits wrapped to 0 exactly
    }
    __syncthreads();

    // last-arriving block finishes (atomic return already holds the full sum)
    if (sm_last && wib == 0) {
        float ws = 0.0f;
        #pragma unroll
        for (int j = 0; j < 8; ++j) {
            const int q = lane + 32 * j;
            if (q < 250) {
                float4 wv = w4[q];
                ws += (wv.x + wv.y) + (wv.z + wv.w);
            }
        }
        ws = wredux(ws);
        if (lane == 0) {
            long long net = (long long)sm_total - ((long long)NBLK * BIAS_LL);
            const float lsum = (float)net * INV_SCALE;
            out[0] = lsum * ((float)C_CLS / ws) * (1.0f / (float)B_ROWS)
                   + A_off * (float)C_CLS;
            atomicExch(&g_acc, 0ull);          // reset for next graph replay
        }
    }
}

// ---------------------------------------------------------------------------
extern "C" void kernel_launch(void* const* d_in, const int* in_sizes, int n_in,
                              void* d_out, int out_size)
{
    const float* logits = (const float*)d_in[0];
    const int*   truth  = (const int*)  d_in[1];
    const float* weight = (const float*)d_in[2];
    float* out = (float*)d_out;

    const double T1 = 0.8, SM = 0.05;
    const double Cd = (double)C_CLS;
    const double y_on  = (1.0 - SM * Cd / (Cd - 1.0)) + SM / (Cd - 1.0);
    const double y_off = SM / (Cd - 1.0);
    auto logt1 = [](double v) { return (pow(v, 0.2) - 1.0) / 0.2; };
    auto Cy = [&](double y) {
        return y * logt1(y + 1e-10) - pow(y, 2.0 - T1) / (2.0 - T1);
    };
    const float A_on  = (float)(Cy(y_on)  + 5.0 * y_on);
    const float A_off = (float)(Cy(y_off) + 5.0 * y_off);
    const float B_on  = (float)(5.0 * y_on);
    const float B_off = (float)(5.0 * y_off);

    bitempered_row_kernel<<<NBLK, 256>>>(logits, truth, weight, out,
                                         A_off, B_off,
                                         A_on - A_off, B_on - B_off);
}

// round 15
// speedup vs baseline: 1.4570x; 1.0277x over previous
#include <cuda_runtime.h>
#include <math.h>

#define B_ROWS 32768
#define C_CLS  1000
#define NBLK   (B_ROWS / 8)

// packed accumulator: bits[63:52] arrival count, bits[51:0] biased fixed-point sum
__device__ unsigned long long g_acc;   // zero-init; self-resets each launch

typedef unsigned long long u64;

#define SCALE_F   268435456.0f           /* 2^28 */
#define INV_SCALE (1.0f / 268435456.0f)
#define BIAS_LL   (1ll << 39)
#define SUB_SCALE 3.90625f               /* 1000/256: subsample -> full Z */
#define S0_BOOT   0.35f                  /* fixed bootstrap start */

__device__ __forceinline__ float frcp(float x) {
    float r; asm("rcp.approx.f32 %0, %1;" : "=f"(r) : "f"(x)); return r;
}
__device__ __forceinline__ float fpow_fast(float x, float p) {
    float lg; asm("lg2.approx.f32 %0, %1;" : "=f"(lg) : "f"(x));
    float e = lg * p;
    float r; asm("ex2.approx.f32 %0, %1;" : "=f"(r) : "f"(e)); return r;
}
__device__ __forceinline__ u64 pk(float x, float y) {
    u64 r; asm("mov.b64 %0, {%1,%2};" : "=l"(r) : "f"(x), "f"(y)); return r;
}
__device__ __forceinline__ void upk(u64 v, float& x, float& y) {
    asm("mov.b64 {%0,%1}, %2;" : "=f"(x), "=f"(y) : "l"(v));
}
__device__ __forceinline__ u64 fma2(u64 a, u64 b, u64 c) {
    u64 d; asm("fma.rn.f32x2 %0, %1, %2, %3;" : "=l"(d) : "l"(a), "l"(b), "l"(c)); return d;
}
__device__ __forceinline__ u64 mul2(u64 a, u64 b) {
    u64 d; asm("mul.rn.f32x2 %0, %1, %2;" : "=l"(d) : "l"(a), "l"(b)); return d;
}
__device__ __forceinline__ u64 add2(u64 a, u64 b) {
    u64 d; asm("add.rn.f32x2 %0, %1, %2;" : "=l"(d) : "l"(a), "l"(b)); return d;
}
__device__ __forceinline__ u64 rcp2(u64 v) {      // 2x MUFU
    float x, y; upk(v, x, y);
    return pk(frcp(x), frcp(y));
}
__device__ __forceinline__ float wredux(float v) {
    #pragma unroll
    for (int o = 16; o; o >>= 1) v += __shfl_xor_sync(0xffffffffu, v, o);
    return v;
}
// 64-bit packed butterfly: reduces both packed floats at once
__device__ __forceinline__ u64 wredux2(u64 v) {
    #pragma unroll
    for (int o = 16; o; o >>= 1)
        v = add2(v, __shfl_xor_sync(0xffffffffu, v, o));
    return v;
}

// packed rcp seed; no cross-field borrow: low field >= bits(nr) for nr in [-3,-1]
#define MAGIC2 0xFEF311C3FEF311C3ULL

// ---------------------------------------------------------------------------
// One warp per row; 32 RAW logits/lane as 16 packed f32x2 regs.  Each pass
// folds u = -0.2(x-mu) into linear constants: -r = (0.2s)x - (1+0.2s*xmax).
// Bootstrap: one subsample pass (pairs 0..3, seed+1-Newton) at s0 accumulating
// Z5s,Z6s -> Newton fixed-point extrapolation -> s_pred; g' from this pass is
// REUSED for the final extrapolation (g' varies slowly; sf err ~2e-4).
// Full pass at s_pred: Z5 + weighted S1,S6,S7 (NO Z6 — reuse gp_boot);
// sf = s_pred + (g - s_pred)/(1 - gp_boot);  c = sf/s_pred - 1:
//   ΣwInv ~ sf*S1,   ΣwInv6 ~ sf^6*(S6 - 6c(S6-S7)).
// Final reductions: two INDEPENDENT packed wredux2 chains (latency overlaps).
// Fence-free packed-u64 atomic finish.
// ---------------------------------------------------------------------------
__global__ __launch_bounds__(256, 4)
void bitempered_row_kernel(const float* __restrict__ logits,
                           const int*   __restrict__ truth,
                           const float* __restrict__ weight,
                           float* __restrict__ out,
                           float A_off, float B_off, float dA, float dB)
{
    __shared__ float sm[8];
    __shared__ u64   sm_total;
    __shared__ int   sm_last;
    const int lane = threadIdx.x & 31;
    const int wib  = threadIdx.x >> 5;
    const int row  = blockIdx.x * 8 + wib;

    const int   t  = truth[row];                       // uniform per warp
    const float xt = logits[(size_t)row * C_CLS + t];  // truth-class logit
    const float wt = __ldg(weight + t);

    const float4* xrow = (const float4*)(logits + (size_t)row * C_CLS);

    u64 x2[16];                                 // raw logits (masked = -inf)
    float xmax = -INFINITY;
    #pragma unroll
    for (int j = 0; j < 8; ++j) {
        const int q = lane + 32 * j;            // float4 index, valid iff q < 250
        float4 v;
        if (q < 250) v = xrow[q];
        else         v = make_float4(-INFINITY, -INFINITY, -INFINITY, -INFINITY);
        x2[2*j]   = pk(v.x, v.y);
        x2[2*j+1] = pk(v.z, v.w);
        xmax = fmaxf(xmax, fmaxf(fmaxf(v.x, v.y), fmaxf(v.z, v.w)));
    }
    #pragma unroll
    for (int o = 16; o; o >>= 1)
        xmax = fmaxf(xmax, __shfl_xor_sync(0xffffffffu, xmax, o));

    const u64 TWO2 = pk(2.0f, 2.0f);

    // ---- Bootstrap: one subsample pass at s0 + Newton FP extrapolation
    float s_pred, gp_boot;
    {
        const float m  = 0.2f * S0_BOOT;
        const float cc = fmaf(m, xmax, 1.0f);   // 1 + 0.2*s0*xmax
        const u64 pm2 = pk(m, m);
        const u64 nc2 = pk(-cc, -cc);
        u64 z5a = pk(0.0f, 0.0f), z6a = z5a;
        #pragma unroll
        for (int i = 0; i < 4; ++i) {           // pairs 0..3: mask-free
            u64 nr2 = fma2(x2[i], pm2, nc2);    // -(1+u*s0) in [-3,-1]
            u64 y   = MAGIC2 - nr2;             // ~5% seed (ALU pipe)
            y = mul2(y, fma2(nr2, y, TWO2));    // 1 Newton (~1e-3)
            u64 q2 = mul2(y, y);
            u64 q4 = mul2(q2, q2);
            z5a = fma2(q4, y, z5a);             // += inv^5
            u64 p6 = mul2(q4, q2);
            z6a = add2(z6a, p6);                // += inv^6
        }
        float a, b, a2, b2;
        upk(z5a, a, b); upk(z6a, a2, b2);
        u64 rZ = wredux2(pk(a + b, a2 + b2));   // all lanes get (Z5s, Z6s)
        float Z5s, Z6s; upk(rZ, Z5s, Z6s);
        const float Z5 = Z5s * SUB_SCALE;
        const float g  = fpow_fast(Z5, -0.2f);                  // g(s0)
        gp_boot = g * (1.0f - Z6s * frcp(Z5s)) * (1.0f / S0_BOOT);
        s_pred  = S0_BOOT + (g - S0_BOOT) * frcp(1.0f - gp_boot);
    }

    // ---- Full pass at s_pred: Z5 + weighted sums S1, S6, S7 (no Z6)
    const float m  = 0.2f * s_pred;
    const float cc = fmaf(m, xmax, 1.0f);       // 1 + 0.2*s_pred*xmax
    const u64 pm2  = pk(m, m);                  // for nr (Newton path)
    const u64 nc2  = pk(-cc, -cc);
    const u64 nm2  = pk(-m, -m);                // for r  (MUFU path)
    const u64 pc2  = pk(cc, cc);
    const float4* w4 = (const float4*)weight;

    u64 z5a = pk(0.0f, 0.0f);
    u64 S1a = z5a, S6a = z5a, S7a = z5a;
    #pragma unroll
    for (int j = 0; j < 8; ++j) {
        const int q = lane + 32 * j;
        float4 wv;
        if (q < 250) wv = w4[q];
        else         wv = make_float4(0.0f, 0.0f, 0.0f, 0.0f);
        u64 w2[2] = { pk(wv.x, wv.y), pk(wv.z, wv.w) };
        #pragma unroll
        for (int h = 0; h < 2; ++h) {
            const int i = 2*j + h;
            u64 y;
            if (i < 14) {                       // mask-free: FMA-pipe Newton
                u64 nr2 = fma2(x2[i], pm2, nc2);     // -(1+u*s)
                y = MAGIC2 - nr2;
                y = mul2(y, fma2(nr2, y, TWO2));
                y = mul2(y, fma2(nr2, y, TWO2));
            } else {                            // MUFU (x=-inf -> r=+inf -> 0)
                u64 r2 = fma2(x2[i], nm2, pc2);
                y = rcp2(r2);
            }
            u64 q2 = mul2(y, y);
            u64 q4 = mul2(q2, q2);
            z5a = fma2(q4, y, z5a);             // Z5 += inv^5
            S1a = fma2(y,  w2[h], S1a);         // += w*inv
            u64 p6 = mul2(q4, q2);
            S6a = fma2(p6, w2[h], S6a);         // += w*inv^6
            u64 p7 = mul2(p6, y);
            S7a = fma2(p7, w2[h], S7a);         // += w*inv^7
        }
    }
    // two independent packed reduction chains (latency overlaps)
    float a, b, a2, b2;
    upk(z5a, a, b); upk(S1a, a2, b2);
    u64 rA = pk(a + b, a2 + b2);                // (Z5, S1)
    upk(S6a, a, b); upk(S7a, a2, b2);
    u64 rB = pk(a + b, a2 + b2);                // (S6, S7)
    #pragma unroll
    for (int o = 16; o; o >>= 1) {
        rA = add2(rA, __shfl_xor_sync(0xffffffffu, rA, o));
        rB = add2(rB, __shfl_xor_sync(0xffffffffu, rB, o));
    }

    if (lane == 0) {
        float Z5, S1, S6, S7;
        upk(rA, Z5, S1);
        upk(rB, S6, S7);
        const float g  = fpow_fast(Z5, -0.2f);                  // g(s_pred)
        const float sf = s_pred + (g - s_pred) * frcp(1.0f - gp_boot);
        const float zp = frcp(sf);                    // u + zp = 1 - 0.2*(x-nc)
        const float c  = fmaf(sf, frcp(s_pred), -1.0f);
        const float sf2 = sf * sf;
        const float sf6 = sf2 * sf2 * sf2;
        const float sumInv  = sf * S1;
        const float sumInv6 = sf6 * fmaf(-6.0f * c, S6 - S7, S6);
        const float ut   = fmaf(xt, -0.2f, 0.2f * xmax);
        const float invt = frcp(ut + zp);
        float acc = fmaf(-B_off, sumInv, sumInv6 * (1.0f / 1.2f));
        acc += wt * fmaf(-dB, invt, dA);
        sm[wib] = acc;
    }
    __syncthreads();

    if (threadIdx.x == 0) {
        float bs = 0.0f;
        #pragma unroll
        for (int i = 0; i < 8; ++i) bs += sm[i];
        long long llv = __float2ll_rn(bs * SCALE_F);        // |llv| << 2^39
        u64 contrib = (1ull << 52) + (u64)(llv + BIAS_LL);
        u64 old = atomicAdd(&g_acc, contrib);
        int last = ((old >> 52) == (u64)(NBLK - 1));
        sm_last = last;
        if (last) sm_total = old + contrib;   // counter bits wrapped to 0 exactly
    }
    __syncthreads();

    // last-arriving block finishes (atomic return already holds the full sum)
    if (sm_last && wib == 0) {
        float ws = 0.0f;
        #pragma unroll
        for (int j = 0; j < 8; ++j) {
            const int q = lane + 32 * j;
            if (q < 250) {
                float4 wv = w4[q];
                ws += (wv.x + wv.y) + (wv.z + wv.w);
            }
        }
        ws = wredux(ws);
        if (lane == 0) {
            long long net = (long long)sm_total - ((long long)NBLK * BIAS_LL);
            const float lsum = (float)net * INV_SCALE;
            out[0] = lsum * ((float)C_CLS / ws) * (1.0f / (float)B_ROWS)
                   + A_off * (float)C_CLS;
            atomicExch(&g_acc, 0ull);          // reset for next graph replay
        }
    }
}

// ---------------------------------------------------------------------------
extern "C" void kernel_launch(void* const* d_in, const int* in_sizes, int n_in,
                              void* d_out, int out_size)
{
    const float* logits = (const float*)d_in[0];
    const int*   truth  = (const int*)  d_in[1];
    const float* weight = (const float*)d_in[2];
    float* out = (float*)d_out;

    const double T1 = 0.8, SM = 0.05;
    const double Cd = (double)C_CLS;
    const double y_on  = (1.0 - SM * Cd / (Cd - 1.0)) + SM / (Cd - 1.0);
    const double y_off = SM / (Cd - 1.0);
    auto logt1 = [](double v) { return (pow(v, 0.2) - 1.0) / 0.2; };
    auto Cy = [&](double y) {
        return y * logt1(y + 1e-10) - pow(y, 2.0 - T1) / (2.0 - T1);
    };
    const float A_on  = (float)(Cy(y_on)  + 5.0 * y_on);
    const float A_off = (float)(Cy(y_off) + 5.0 * y_off);
    const float B_on  = (float)(5.0 * y_on);
    const float B_off = (float)(5.0 * y_off);

    bitempered_row_kernel<<<NBLK, 256>>>(logits, truth, weight, out,
                                         A_off, B_off,
                                         A_on - A_off, B_on - B_off);
}